// round 4
// baseline (speedup 1.0000x reference)
#include <cuda_runtime.h>

// Problem constants (fixed by the dataset shapes)
#define P_ 2
#define B_ 96
#define A_ 32
#define N_ (B_ * A_)      // 3072
#define MD_ 4
#define MA_ 4
#define NPOLB_ 8
#define NSLOT_ (P_ * B_ * NPOLB_)   // 1536
#define C_LK_ 0.0897935610625833f

#define PAIR_THREADS_ 128
#define JPT_ 3
#define CHUNK_ (PAIR_THREADS_ * JPT_)   // 384
#define NCHUNK_ (N_ / CHUNK_)           // 8

// Scratch (device globals — no allocation allowed)
__device__ float4 g_posr[P_ * N_];          // (x,y,z,rj) per atom
__device__ float  g_vol[P_ * N_];           // volj, 0 for hydrogens
__device__ float4 g_slot[NSLOT_ * 4];       // per-slot record, 4x float4
__device__ unsigned g_msep_ok[P_ * B_][4];  // bit bj: min_sep(b,bj) >= 4

// ---------------------------------------------------------------------------
// Setup: bid<24 pack atoms; bid 24..29 build slot records (+pd bitmask);
// bid 30: inter-block sep bitmasks + zero the output.
// ---------------------------------------------------------------------------
__global__ __launch_bounds__(256) void setup_kernel(
    const float* __restrict__ coords,        // (P,N,3)
    const int*   __restrict__ block_type,    // (P,B)
    const int*   __restrict__ min_sep,       // (P,B,B)
    const int*   __restrict__ all_bonds,     // (NT,A,2)
    const int*   __restrict__ bond_ranges,   // (NT,A,2)
    const int*   __restrict__ n_donH,        // (NT)
    const int*   __restrict__ n_acc,         // (NT)
    const int*   __restrict__ donH_inds,     // (NT,MD)
    const int*   __restrict__ don_hvy_inds,  // (NT,MD)
    const int*   __restrict__ acc_inds,      // (NT,MA)
    const int*   __restrict__ hyb,           // (NT,MA)
    const int*   __restrict__ is_h,          // (NT,A)
    const float* __restrict__ lk_params,     // (NT,A,4)
    const int*   __restrict__ path_dist,     // (NT,A,A)
    const float* __restrict__ wgen_glob,     // (2): wdist, wang
    const float* __restrict__ sp2_tors,
    const float* __restrict__ sp3_tors,
    const float* __restrict__ ring_tors,
    float*       __restrict__ out)
{
    const int tid = threadIdx.x;
    const int bid = blockIdx.x;

    if (bid < (P_ * N_) / 256) {
        // ---- pack j-atom stream ----
        const int idx = bid * 256 + tid;          // [0, P*N)
        const int p  = idx / N_;
        const int jj = idx - p * N_;
        const int bj = jj >> 5;
        const int aj = jj & 31;
        const int tj = block_type[p * B_ + bj];
        const float x = coords[3 * idx + 0];
        const float y = coords[3 * idx + 1];
        const float z = coords[3 * idx + 2];
        const float rj   = lk_params[(tj * A_ + aj) * 4 + 0];
        const float volj = lk_params[(tj * A_ + aj) * 4 + 3];
        const bool heavy = (is_h[tj * A_ + aj] == 0);
        g_posr[idx] = make_float4(x, y, z, rj);
        g_vol[idx]  = heavy ? volj : 0.0f;
        return;
    }

    if (bid == (P_ * N_) / 256 + NSLOT_ / 256) {
        // ---- inter-block sep bitmasks + output zero ----
        if (tid < P_ * B_) {
            const int row = tid;
            unsigned w[4] = {0u, 0u, 0u, 0u};
            for (int bj = 0; bj < B_; bj++) {
                if (min_sep[row * B_ + bj] >= 4)
                    w[bj >> 5] |= (1u << (bj & 31));
            }
            g_msep_ok[row][0] = w[0];
            g_msep_ok[row][1] = w[1];
            g_msep_ok[row][2] = w[2];
            g_msep_ok[row][3] = w[3];
        } else if (tid >= P_ * B_ && tid < P_ * B_ + 2 * P_) {
            out[tid - P_ * B_] = 0.0f;
        }
        return;
    }

    // ---- slot records ----
    const int s = (bid - (P_ * N_) / 256) * 256 + tid;   // [0, 1536)
    const int p = s / (B_ * NPOLB_);
    const int r = s - p * (B_ * NPOLB_);
    const int b = r >> 3;
    const int k = r & 7;
    const int t = block_type[p * B_ + b];
    const float* cblk = coords + (size_t)(p * N_ + b * A_) * 3;
    const float wdist = wgen_glob[0];

    int valid, ai;
    float px, py, pz;
    float w0x, w0y, w0z, w1x, w1y, w1z;
    if (k < MD_) {
        valid = (k < n_donH[t]) ? 1 : 0;
        const int hv = don_hvy_inds[t * MD_ + k];
        const int hh = donH_inds[t * MD_ + k];
        ai = hv;
        px = cblk[3 * hv + 0]; py = cblk[3 * hv + 1]; pz = cblk[3 * hv + 2];
        float dx = cblk[3 * hh + 0] - px;
        float dy = cblk[3 * hh + 1] - py;
        float dz = cblk[3 * hh + 2] - pz;
        const float inv = rsqrtf(dx * dx + dy * dy + dz * dz + 1e-12f);
        w0x = px + wdist * dx * inv;
        w0y = py + wdist * dy * inv;
        w0z = pz + wdist * dz * inv;
        w1x = 1.0e4f; w1y = 1.0e4f; w1z = 1.0e4f;   // masked 2nd water
    } else {
        const int m = k - MD_;
        valid = (m < n_acc[t]) ? 1 : 0;
        const int c = acc_inds[t * MA_ + m];
        ai = c;
        const int r0c = bond_ranges[(t * A_ + c) * 2 + 0];
        const int bs  = all_bonds[(t * A_ + r0c) * 2 + 1];
        const int r0b = bond_ranges[(t * A_ + bs) * 2 + 0];
        const int b2  = all_bonds[(t * A_ + r0b) * 2 + 1];
        px = cblk[3 * c + 0]; py = cblk[3 * c + 1]; pz = cblk[3 * c + 2];
        const float bx = cblk[3 * bs + 0], by = cblk[3 * bs + 1], bz = cblk[3 * bs + 2];
        const float ax = cblk[3 * b2 + 0], ay = cblk[3 * b2 + 1], az = cblk[3 * b2 + 2];
        float e1x = px - bx, e1y = py - by, e1z = pz - bz;
        float inv = rsqrtf(e1x * e1x + e1y * e1y + e1z * e1z + 1e-12f);
        e1x *= inv; e1y *= inv; e1z *= inv;
        const float mx = bx - ax, my = by - ay, mz = bz - az;
        float nx = my * e1z - mz * e1y;
        float ny = mz * e1x - mx * e1z;
        float nz = mx * e1y - my * e1x;
        inv = rsqrtf(nx * nx + ny * ny + nz * nz + 1e-12f);
        nx *= inv; ny *= inv; nz *= inv;
        const float e2x = ny * e1z - nz * e1y;
        const float e2y = nz * e1x - nx * e1z;
        const float e2z = nx * e1y - ny * e1x;
        const float wang = wgen_glob[1];
        const float ct = cosf(wang), st = sinf(wang);
        const int h = hyb[t * MA_ + m];
        const float* tors = (h == 0) ? sp2_tors : ((h == 1) ? sp3_tors : ring_tors);
        const float c0 = cosf(tors[0]), sn0 = sinf(tors[0]);
        const float c1 = cosf(tors[1]), sn1 = sinf(tors[1]);
        const float a1 = -wdist * ct;
        const float a2 = wdist * st;
        w0x = px + a1 * e1x + a2 * (c0 * e2x + sn0 * nx);
        w0y = py + a1 * e1y + a2 * (c0 * e2y + sn0 * ny);
        w0z = pz + a1 * e1z + a2 * (c0 * e2z + sn0 * nz);
        w1x = px + a1 * e1x + a2 * (c1 * e2x + sn1 * nx);
        w1y = py + a1 * e1y + a2 * (c1 * e2y + sn1 * ny);
        w1z = pz + a1 * e1z + a2 * (c1 * e2z + sn1 * nz);
    }
    const float* pp = lk_params + (size_t)(t * A_ + ai) * 4;
    const float ri = pp[0], dgi = pp[1], lami = pp[2];
    // intra-block sep>=4 bitmask over the 32 atoms of this block
    unsigned pdmask = 0u;
    const int* pdrow = path_dist + (t * A_ + ai) * A_;
    for (int aj = 0; aj < A_; aj++)
        pdmask |= (pdrow[aj] >= 4) ? (1u << aj) : 0u;
    g_slot[s * 4 + 0] = make_float4(px, py, pz, ri);
    g_slot[s * 4 + 1] = make_float4(w0x, w0y, w0z, 1.0f / lami);
    g_slot[s * 4 + 2] = make_float4(w1x, w1y, w1z, C_LK_ * dgi / lami);
    g_slot[s * 4 + 3] = make_float4(__int_as_float(valid), __uint_as_float(pdmask),
                                    0.0f, 0.0f);
}

// ---------------------------------------------------------------------------
// Pair kernel: CTA = (pose-block, j-chunk). 8 slots of the block vs 384 j.
// j-atoms live in registers (3/thread), reused across all 8 slots.
// ---------------------------------------------------------------------------
__global__ __launch_bounds__(PAIR_THREADS_) void pair_kernel(
    const float* __restrict__ lkb_glob,      // cutoff, ramp2, d2_low
    float*       __restrict__ out)           // (2,P)
{
    const int bid = blockIdx.x;
    const int pb = bid / NCHUNK_;            // [0, P*B)
    const int chunk = bid - pb * NCHUNK_;
    const int p = pb / B_;
    const int b = pb - p * B_;
    const int tid = threadIdx.x;

    __shared__ float4 s_slot[NPOLB_ * 4];
    __shared__ unsigned s_msep[4];
    if (tid < NPOLB_ * 4) s_slot[tid] = g_slot[pb * (NPOLB_ * 4) + tid];
    if (tid >= 32 && tid < 36) s_msep[tid - 32] = g_msep_ok[pb][tid - 32];
    __syncthreads();

    const float cutoff = lkb_glob[0];
    const float ramp2  = lkb_glob[1];
    const float cut2   = cutoff * cutoff;
    const float inv_ramp2 = 1.0f / ramp2;
    const float thresh = lkb_glob[2] + ramp2;

    // load this thread's j-atoms into registers
    const int j0 = chunk * CHUNK_ + tid;
    float4 pr[JPT_];
    float  v[JPT_];
    unsigned aj[JPT_];
    bool   same[JPT_];
    bool   interok[JPT_];
#pragma unroll
    for (int i = 0; i < JPT_; i++) {
        const int j = j0 + i * PAIR_THREADS_;
        pr[i] = g_posr[p * N_ + j];
        v[i]  = g_vol[p * N_ + j];
        const int bj = j >> 5;
        aj[i] = (unsigned)(j & 31);
        same[i] = (bj == b);
        interok[i] = (s_msep[bj >> 5] >> (bj & 31)) & 1u;
    }

    float acc0 = 0.0f, acc1 = 0.0f;
#pragma unroll 2
    for (int k = 0; k < NPOLB_; k++) {
        const float4 a3 = s_slot[k * 4 + 3];
        if (!__float_as_int(a3.x)) continue;       // uniform skip
        const unsigned pdmask = __float_as_uint(a3.y);
        const float4 a0 = s_slot[k * 4 + 0];
        const float4 a1 = s_slot[k * 4 + 1];
        const float4 a2 = s_slot[k * 4 + 2];
#pragma unroll
        for (int i = 0; i < JPT_; i++) {
            const float dx = a0.x - pr[i].x;
            const float dy = a0.y - pr[i].y;
            const float dz = a0.z - pr[i].z;
            const float d2 = fmaxf(dx * dx + dy * dy + dz * dz, 0.01f);
            const bool sepok = same[i] ? ((pdmask >> aj[i]) & 1u) : interok[i];
            if (d2 < cut2 && v[i] > 0.0f && sepok) {
                const float d = sqrtf(d2);
                const float x = (d - a0.w - pr[i].w) * a1.w;
                const float lk = __fdividef(a2.w * v[i] * __expf(-x * x), d2);
                const float u0 = a1.x - pr[i].x, u1 = a1.y - pr[i].y, u2 = a1.z - pr[i].z;
                const float q0 = a2.x - pr[i].x, q1 = a2.y - pr[i].y, q2 = a2.z - pr[i].z;
                const float d2w0 = u0 * u0 + u1 * u1 + u2 * u2;
                const float d2w1 = q0 * q0 + q1 * q1 + q2 * q2;
                const float d2wmin = fminf(d2w0, d2w1);
                const float wt = __saturatef((thresh - d2wmin) * inv_ramp2);
                const float frac = wt * wt * (3.0f - 2.0f * wt);
                acc0 += lk;
                acc1 += lk * frac;
            }
        }
    }

    // warp reduce -> smem -> 2 atomics per CTA
    const int lane = tid & 31;
    const int wid = tid >> 5;
#pragma unroll
    for (int o = 16; o > 0; o >>= 1) {
        acc0 += __shfl_down_sync(0xFFFFFFFFu, acc0, o);
        acc1 += __shfl_down_sync(0xFFFFFFFFu, acc1, o);
    }
    __shared__ float r0[PAIR_THREADS_ / 32], r1[PAIR_THREADS_ / 32];
    if (lane == 0) { r0[wid] = acc0; r1[wid] = acc1; }
    __syncthreads();
    if (tid == 0) {
        float t0 = 0.0f, t1 = 0.0f;
#pragma unroll
        for (int w = 0; w < PAIR_THREADS_ / 32; w++) { t0 += r0[w]; t1 += r1[w]; }
        atomicAdd(&out[p], t0);          // out[0, p]
        atomicAdd(&out[P_ + p], t1);     // out[1, p]
    }
}

extern "C" void kernel_launch(void* const* d_in, const int* in_sizes, int n_in,
                              void* d_out, int out_size) {
    const float* coords       = (const float*)d_in[0];
    const int*   block_type   = (const int*)  d_in[1];
    const int*   min_sep      = (const int*)  d_in[2];
    // d_in[3] = bt_n_atoms (unused)
    const int*   all_bonds    = (const int*)  d_in[4];
    const int*   bond_ranges  = (const int*)  d_in[5];
    const int*   n_donH       = (const int*)  d_in[6];
    const int*   n_acc        = (const int*)  d_in[7];
    const int*   donH_inds    = (const int*)  d_in[8];
    const int*   don_hvy_inds = (const int*)  d_in[9];
    const int*   acc_inds     = (const int*)  d_in[10];
    const int*   hyb          = (const int*)  d_in[11];
    const int*   is_h         = (const int*)  d_in[12];
    const float* lk_params    = (const float*)d_in[13];
    const int*   path_dist    = (const int*)  d_in[14];
    const float* lkb_glob     = (const float*)d_in[15];
    const float* wgen_glob    = (const float*)d_in[16];
    const float* sp2_tors     = (const float*)d_in[17];
    const float* sp3_tors     = (const float*)d_in[18];
    const float* ring_tors    = (const float*)d_in[19];
    float* out = (float*)d_out;

    const int setup_blocks = (P_ * N_) / 256 + NSLOT_ / 256 + 1;  // 24 + 6 + 1
    setup_kernel<<<setup_blocks, 256>>>(
        coords, block_type, min_sep, all_bonds, bond_ranges, n_donH, n_acc,
        donH_inds, don_hvy_inds, acc_inds, hyb, is_h, lk_params, path_dist,
        wgen_glob, sp2_tors, sp3_tors, ring_tors, out);

    pair_kernel<<<P_ * B_ * NCHUNK_, PAIR_THREADS_>>>(lkb_glob, out);
}

// round 6
// speedup vs baseline: 1.2162x; 1.2162x over previous
#include <cuda_runtime.h>

// Problem constants (fixed by the dataset shapes)
#define P_ 2
#define B_ 96
#define A_ 32
#define N_ (B_ * A_)      // 3072
#define MD_ 4
#define MA_ 4
#define NPOLB_ 8
#define C_LK_ 0.0897935610625833f

#define THREADS_ 256
#define JPT_ 3
#define CHUNK_ (THREADS_ * JPT_)        // 768
#define NCHUNK_ (N_ / CHUNK_)           // 4
#define GRID_ (P_ * B_ * NCHUNK_)       // 768

// Self-resetting cross-CTA accumulator (device globals start at zero).
__device__ float g_acc[4];
__device__ unsigned g_done;

__global__ __launch_bounds__(THREADS_) void lkball_fused_kernel(
    const float* __restrict__ coords,        // (P,N,3)
    const int*   __restrict__ block_type,    // (P,B)
    const int*   __restrict__ min_sep,       // (P,B,B)
    const int*   __restrict__ all_bonds,     // (NT,A,2)
    const int*   __restrict__ bond_ranges,   // (NT,A,2)
    const int*   __restrict__ n_donH,        // (NT)
    const int*   __restrict__ n_acc,         // (NT)
    const int*   __restrict__ donH_inds,     // (NT,MD)
    const int*   __restrict__ don_hvy_inds,  // (NT,MD)
    const int*   __restrict__ acc_inds,      // (NT,MA)
    const int*   __restrict__ hyb,           // (NT,MA)
    const int*   __restrict__ is_h,          // (NT,A)
    const float* __restrict__ lk_params,     // (NT,A,4)
    const int*   __restrict__ path_dist,     // (NT,A,A)
    const float* __restrict__ lkb_glob,      // cutoff, ramp2, d2_low
    const float* __restrict__ wgen_glob,     // wdist, wang
    const float* __restrict__ sp2_tors,
    const float* __restrict__ sp3_tors,
    const float* __restrict__ ring_tors,
    float*       __restrict__ out)           // (2,P)
{
    const int bid = blockIdx.x;
    const int pb = bid / NCHUNK_;            // [0, P*B)
    const int chunk = bid - pb * NCHUNK_;
    const int p = pb / B_;
    const int b = pb - p * B_;
    const int tid = threadIdx.x;

    // slot records in shared: [k][0]=pos+ri, [1]=w0+invlam, [2]=w1+coef,
    // s_meta[k] = valid, s_pdm[k] = intra-block sep>=4 bitmask
    __shared__ float4 s_slot[NPOLB_][3];
    __shared__ int s_meta[NPOLB_];
    __shared__ unsigned s_pdm[NPOLB_];

    const int t = block_type[p * B_ + b];

    // ---- slot prologue: threads 0..7 build their slot ----
    if (tid < NPOLB_) {
        const int k = tid;
        const float* cblk = coords + (size_t)(p * N_ + b * A_) * 3;
        const float wdist = wgen_glob[0];
        int valid, ai;
        float px, py, pz;
        float w0x, w0y, w0z, w1x, w1y, w1z;
        if (k < MD_) {
            valid = (k < n_donH[t]) ? 1 : 0;
            const int hv = don_hvy_inds[t * MD_ + k];
            const int hh = donH_inds[t * MD_ + k];
            ai = hv;
            px = cblk[3 * hv + 0]; py = cblk[3 * hv + 1]; pz = cblk[3 * hv + 2];
            float dx = cblk[3 * hh + 0] - px;
            float dy = cblk[3 * hh + 1] - py;
            float dz = cblk[3 * hh + 2] - pz;
            const float inv = rsqrtf(dx * dx + dy * dy + dz * dz + 1e-12f);
            w0x = px + wdist * dx * inv;
            w0y = py + wdist * dy * inv;
            w0z = pz + wdist * dz * inv;
            w1x = 1.0e4f; w1y = 1.0e4f; w1z = 1.0e4f;   // masked 2nd water
        } else {
            const int m = k - MD_;
            valid = (m < n_acc[t]) ? 1 : 0;
            const int c = acc_inds[t * MA_ + m];
            ai = c;
            const int r0c = bond_ranges[(t * A_ + c) * 2 + 0];
            const int bs  = all_bonds[(t * A_ + r0c) * 2 + 1];
            const int r0b = bond_ranges[(t * A_ + bs) * 2 + 0];
            const int b2  = all_bonds[(t * A_ + r0b) * 2 + 1];
            px = cblk[3 * c + 0]; py = cblk[3 * c + 1]; pz = cblk[3 * c + 2];
            const float bx = cblk[3 * bs + 0], by = cblk[3 * bs + 1], bz = cblk[3 * bs + 2];
            const float ax = cblk[3 * b2 + 0], ay = cblk[3 * b2 + 1], az = cblk[3 * b2 + 2];
            float e1x = px - bx, e1y = py - by, e1z = pz - bz;
            float inv = rsqrtf(e1x * e1x + e1y * e1y + e1z * e1z + 1e-12f);
            e1x *= inv; e1y *= inv; e1z *= inv;
            const float mx = bx - ax, my = by - ay, mz = bz - az;
            float nx = my * e1z - mz * e1y;
            float ny = mz * e1x - mx * e1z;
            float nz = mx * e1y - my * e1x;
            inv = rsqrtf(nx * nx + ny * ny + nz * nz + 1e-12f);
            nx *= inv; ny *= inv; nz *= inv;
            const float e2x = ny * e1z - nz * e1y;
            const float e2y = nz * e1x - nx * e1z;
            const float e2z = nx * e1y - ny * e1x;
            const float wang = wgen_glob[1];
            const float ct = cosf(wang), st = sinf(wang);
            const int h = hyb[t * MA_ + m];
            const float* tors = (h == 0) ? sp2_tors : ((h == 1) ? sp3_tors : ring_tors);
            const float c0 = cosf(tors[0]), sn0 = sinf(tors[0]);
            const float c1 = cosf(tors[1]), sn1 = sinf(tors[1]);
            const float a1 = -wdist * ct;
            const float a2 = wdist * st;
            w0x = px + a1 * e1x + a2 * (c0 * e2x + sn0 * nx);
            w0y = py + a1 * e1y + a2 * (c0 * e2y + sn0 * ny);
            w0z = pz + a1 * e1z + a2 * (c0 * e2z + sn0 * nz);
            w1x = px + a1 * e1x + a2 * (c1 * e2x + sn1 * nx);
            w1y = py + a1 * e1y + a2 * (c1 * e2y + sn1 * ny);
            w1z = pz + a1 * e1z + a2 * (c1 * e2z + sn1 * nz);
        }
        const float* pp = lk_params + (size_t)(t * A_ + ai) * 4;
        const float ri = pp[0], dgi = pp[1], lami = pp[2];
        // intra-block sep>=4 bitmask via int4 loads
        unsigned pdmask = 0u;
        const int4* pdrow = (const int4*)(path_dist + (t * A_ + ai) * A_);
#pragma unroll
        for (int q = 0; q < 8; q++) {
            const int4 pd4 = pdrow[q];
            pdmask |= (pd4.x >= 4 ? 1u : 0u) << (4 * q + 0);
            pdmask |= (pd4.y >= 4 ? 1u : 0u) << (4 * q + 1);
            pdmask |= (pd4.z >= 4 ? 1u : 0u) << (4 * q + 2);
            pdmask |= (pd4.w >= 4 ? 1u : 0u) << (4 * q + 3);
        }
        s_slot[k][0] = make_float4(px, py, pz, ri);
        s_slot[k][1] = make_float4(w0x, w0y, w0z, 1.0f / lami);
        s_slot[k][2] = make_float4(w1x, w1y, w1z, C_LK_ * dgi / lami);
        s_meta[k] = valid;
        s_pdm[k] = pdmask;
    }

    // ---- j prologue: each thread loads 3 raw j-atoms ----
    const float cutoff = lkb_glob[0];
    const float ramp2  = lkb_glob[1];
    const float cut2   = cutoff * cutoff;
    const float inv_ramp2 = 1.0f / ramp2;
    const float thresh = lkb_glob[2] + ramp2;

    const int j0 = chunk * CHUNK_ + tid;
    float jx[JPT_], jy[JPT_], jz[JPT_], jr[JPT_], jv[JPT_];
    int jbj[JPT_], jaj[JPT_];
#pragma unroll
    for (int i = 0; i < JPT_; i++) {
        const int j = j0 + i * THREADS_;
        const int bj = j >> 5;
        const int aj = j & 31;
        jbj[i] = bj; jaj[i] = aj;
        const int tj = block_type[p * B_ + bj];
        const float* cj = coords + (size_t)(p * N_ + j) * 3;
        jx[i] = cj[0]; jy[i] = cj[1]; jz[i] = cj[2];
        jr[i] = lk_params[(tj * A_ + aj) * 4 + 0];
        const float volj = lk_params[(tj * A_ + aj) * 4 + 3];
        jv[i] = (is_h[tj * A_ + aj] == 0) ? volj : 0.0f;
    }
    __syncthreads();

    // per-j 8-bit slot mask: sep ok (+vol>0) for each slot. warp-uniform branch.
    unsigned jm[JPT_];
#pragma unroll
    for (int i = 0; i < JPT_; i++) {
        unsigned m;
        if (jv[i] <= 0.0f) {
            m = 0u;
        } else if (jbj[i] == b) {
            m = 0u;
            const unsigned bit = 1u << jaj[i];
#pragma unroll
            for (int k = 0; k < NPOLB_; k++)
                m |= ((s_pdm[k] & bit) ? 1u : 0u) << k;
        } else {
            m = (min_sep[(p * B_ + b) * B_ + jbj[i]] >= 4) ? 0xFFu : 0u;
        }
        jm[i] = m;
    }

    // ---- pair loop: 8 slots x JPT j ----
    float acc0 = 0.0f, acc1 = 0.0f;
#pragma unroll 2
    for (int k = 0; k < NPOLB_; k++) {
        if (!s_meta[k]) continue;                 // uniform skip
        const float4 a0 = s_slot[k][0];
        const float4 a1 = s_slot[k][1];
        const float4 a2 = s_slot[k][2];
        const unsigned kbit = 1u << k;
#pragma unroll
        for (int i = 0; i < JPT_; i++) {
            const float dx = a0.x - jx[i];
            const float dy = a0.y - jy[i];
            const float dz = a0.z - jz[i];
            const float d2 = fmaxf(dx * dx + dy * dy + dz * dz, 0.01f);
            if (d2 < cut2 && (jm[i] & kbit)) {
                const float d = sqrtf(d2);
                const float x = (d - a0.w - jr[i]) * a1.w;
                const float lk = __fdividef(a2.w * jv[i] * __expf(-x * x), d2);
                const float u0 = a1.x - jx[i], u1 = a1.y - jy[i], u2 = a1.z - jz[i];
                const float q0 = a2.x - jx[i], q1 = a2.y - jy[i], q2 = a2.z - jz[i];
                const float d2w0 = u0 * u0 + u1 * u1 + u2 * u2;
                const float d2w1 = q0 * q0 + q1 * q1 + q2 * q2;
                const float d2wmin = fminf(d2w0, d2w1);
                const float wt = __saturatef((thresh - d2wmin) * inv_ramp2);
                const float frac = wt * wt * (3.0f - 2.0f * wt);
                acc0 += lk;
                acc1 += lk * frac;
            }
        }
    }

    // ---- reduction: warp shuffle -> smem -> 2 atomics per CTA ----
    const int lane = tid & 31;
    const int wid = tid >> 5;
#pragma unroll
    for (int o = 16; o > 0; o >>= 1) {
        acc0 += __shfl_down_sync(0xFFFFFFFFu, acc0, o);
        acc1 += __shfl_down_sync(0xFFFFFFFFu, acc1, o);
    }
    __shared__ float r0[THREADS_ / 32], r1[THREADS_ / 32];
    if (lane == 0) { r0[wid] = acc0; r1[wid] = acc1; }
    __syncthreads();
    if (tid == 0) {
        float t0 = 0.0f, t1 = 0.0f;
#pragma unroll
        for (int w = 0; w < THREADS_ / 32; w++) { t0 += r0[w]; t1 += r1[w]; }
        atomicAdd(&g_acc[p], t0);
        atomicAdd(&g_acc[2 + p], t1);
        __threadfence();
        const unsigned d = atomicAdd(&g_done, 1u);
        if (d == GRID_ - 1u) {
            // last CTA: publish result and reset accumulators for next replay
            out[0] = atomicExch(&g_acc[0], 0.0f);
            out[1] = atomicExch(&g_acc[1], 0.0f);
            out[2] = atomicExch(&g_acc[2], 0.0f);
            out[3] = atomicExch(&g_acc[3], 0.0f);
            atomicExch(&g_done, 0u);
        }
    }
}

extern "C" void kernel_launch(void* const* d_in, const int* in_sizes, int n_in,
                              void* d_out, int out_size) {
    const float* coords       = (const float*)d_in[0];
    const int*   block_type   = (const int*)  d_in[1];
    const int*   min_sep      = (const int*)  d_in[2];
    // d_in[3] = bt_n_atoms (unused)
    const int*   all_bonds    = (const int*)  d_in[4];
    const int*   bond_ranges  = (const int*)  d_in[5];
    const int*   n_donH       = (const int*)  d_in[6];
    const int*   n_acc        = (const int*)  d_in[7];
    const int*   donH_inds    = (const int*)  d_in[8];
    const int*   don_hvy_inds = (const int*)  d_in[9];
    const int*   acc_inds     = (const int*)  d_in[10];
    const int*   hyb          = (const int*)  d_in[11];
    const int*   is_h         = (const int*)  d_in[12];
    const float* lk_params    = (const float*)d_in[13];
    const int*   path_dist    = (const int*)  d_in[14];
    const float* lkb_glob     = (const float*)d_in[15];
    const float* wgen_glob    = (const float*)d_in[16];
    const float* sp2_tors     = (const float*)d_in[17];
    const float* sp3_tors     = (const float*)d_in[18];
    const float* ring_tors    = (const float*)d_in[19];
    float* out = (float*)d_out;

    lkball_fused_kernel<<<GRID_, THREADS_>>>(
        coords, block_type, min_sep, all_bonds, bond_ranges, n_donH, n_acc,
        donH_inds, don_hvy_inds, acc_inds, hyb, is_h, lk_params, path_dist,
        lkb_glob, wgen_glob, sp2_tors, sp3_tors, ring_tors, out);
}